// round 3
// baseline (speedup 1.0000x reference)
#include <cuda_runtime.h>
#include <cstdint>

// ---------------------------------------------------------------------------
// PingHead on sm_103 (baseline target -> legacy mma.sync tf32 path).
// gi = x @ W_ih^T : M=65536, N=384, K=1024 ; fused GRU-gate epilogue.
// R3: zero cvts in the MMA inner loop:
//   - W pre-converted to tf32 once into __device__ global (cp.async raw)
//   - x LDG->reg one chunk ahead, cvt.rna at STS time
// ---------------------------------------------------------------------------

#define KCHUNKS 32
#define A_BYTES (128 * 128)                 // 128 rows x 32 f32
#define B_BYTES (384 * 128)                 // 384 rows x 32 f32
#define STAGE_BYTES (A_BYTES + B_BYTES)     // 64 KB
#define ROWP 385                            // gi row stride (floats)
#define GI_BYTES (128 * ROWP * 4)
#define SMEM_DYN (GI_BYTES + 1024)

__device__ float g_wtf32[384 * 1024];       // W_ih pre-rounded to tf32

__device__ __forceinline__ uint32_t smem_u32(const void* p) {
    uint32_t a;
    asm("{ .reg .u64 t; cvta.to.shared.u64 t, %1; cvt.u32.u64 %0, t; }" : "=r"(a) : "l"(p));
    return a;
}

__device__ __forceinline__ void cp_async16(uint32_t dst, const void* src) {
    asm volatile("cp.async.cg.shared.global [%0], [%1], 16;" :: "r"(dst), "l"(src) : "memory");
}
#define CP_COMMIT() asm volatile("cp.async.commit_group;" ::: "memory")
#define CP_WAIT1()  asm volatile("cp.async.wait_group 1;" ::: "memory")
#define CP_WAIT0()  asm volatile("cp.async.wait_group 0;" ::: "memory")

__device__ __forceinline__ void ldsm4(uint32_t* r, uint32_t addr) {
    asm volatile("ldmatrix.sync.aligned.m8n8.x4.shared.b16 {%0,%1,%2,%3}, [%4];"
                 : "=r"(r[0]), "=r"(r[1]), "=r"(r[2]), "=r"(r[3]) : "r"(addr));
}

__device__ __forceinline__ uint32_t cvt_tf32f(float f) {
    uint32_t r;
    asm("cvt.rna.tf32.f32 %0, %1;" : "=r"(r) : "f"(f));
    return r;
}

__device__ __forceinline__ void mma_tf32(float* d, const uint32_t* a, const uint32_t* b) {
    asm volatile("mma.sync.aligned.m16n8k8.row.col.f32.tf32.tf32.f32 "
                 "{%0,%1,%2,%3},{%4,%5,%6,%7},{%8,%9},{%0,%1,%2,%3};"
                 : "+f"(d[0]), "+f"(d[1]), "+f"(d[2]), "+f"(d[3])
                 : "r"(a[0]), "r"(a[1]), "r"(a[2]), "r"(a[3]), "r"(b[0]), "r"(b[1]));
}

// --- pre-kernel: round W to tf32 (runs once per replay, ~2us) ---
__global__ void __launch_bounds__(256) wconv_kernel(const float* __restrict__ w) {
    const int i = (blockIdx.x * 256 + threadIdx.x) * 4;
    const float4 v = *reinterpret_cast<const float4*>(w + i);
    uint4 o = make_uint4(cvt_tf32f(v.x), cvt_tf32f(v.y), cvt_tf32f(v.z), cvt_tf32f(v.w));
    *reinterpret_cast<uint4*>(g_wtf32 + i) = o;
}

__global__ void __launch_bounds__(256, 1)
ping_head_kernel(const float* __restrict__ x,
                 const float* __restrict__ b_ih,
                 const float* __restrict__ b_hh,
                 const float* __restrict__ lin_w,
                 const float* __restrict__ lin_b,
                 float* __restrict__ out) {
    extern __shared__ char dsm[];
    __shared__ float s_br[128], s_bz[128], s_bni[128], s_bnh[128], s_lw[128];

    const int tid = threadIdx.x;
    const int wid = tid >> 5;
    const int lane = tid & 31;
    const int m0 = blockIdx.x * 128;

    const uint32_t dsm_u = smem_u32(dsm);
    const uint32_t sb = (dsm_u + 1023u) & ~1023u;   // 1KB-aligned smem base
    char* sb_ptr = dsm + (sb - dsm_u);

    if (tid < 128) {
        s_br[tid]  = b_ih[tid] + b_hh[tid];
        s_bz[tid]  = b_ih[128 + tid] + b_hh[128 + tid];
        s_bni[tid] = b_ih[256 + tid];
        s_bnh[tid] = b_hh[256 + tid];
        s_lw[tid]  = lin_w[tid];
    }

    // ---- A path: LDG one chunk ahead into regs, cvt at STS ----
    const int a_row = tid >> 3;              // 0..127 (fixed per thread, 4 rows apart... no: tid/8)
    const int a_c   = tid & 7;
    float4 xb[4];

    auto ldgA = [&](int kc) {
        const int koff = kc * 32;
#pragma unroll
        for (int i = 0; i < 4; i++) {
            const int row = a_row + i * 32;
            xb[i] = *reinterpret_cast<const float4*>(
                x + (size_t)(m0 + row) * 1024 + koff + a_c * 4);
        }
    };
    auto stsA = [&](int kc) {
        char* stage = sb_ptr + (kc % 3) * STAGE_BYTES;
#pragma unroll
        for (int i = 0; i < 4; i++) {
            const int row = a_row + i * 32;
            const uint32_t doff = (uint32_t)(row * 128) +
                                  (((uint32_t)(a_c * 16)) ^ ((uint32_t)(row & 7) << 4));
            uint4 o = make_uint4(cvt_tf32f(xb[i].x), cvt_tf32f(xb[i].y),
                                 cvt_tf32f(xb[i].z), cvt_tf32f(xb[i].w));
            *reinterpret_cast<uint4*>(stage + doff) = o;
        }
    };
    auto cpB = [&](int kc) {
        const uint32_t sbase = sb + (uint32_t)(kc % 3) * STAGE_BYTES + A_BYTES;
        const int koff = kc * 32;
#pragma unroll
        for (int ch = 0; ch < 12; ch++) {
            const int bi = tid + ch * 256;
            const int row = bi >> 3, c = bi & 7;
            const uint32_t doff = (uint32_t)(row * 128) +
                                  (((uint32_t)(c * 16)) ^ ((uint32_t)(row & 7) << 4));
            cp_async16(sbase + doff, g_wtf32 + (size_t)row * 1024 + koff + c * 4);
        }
    };

    // ---- per-thread ldmatrix addressing (2m x 4n warp grid) ----
    const int warp_m = wid >> 2;
    const int warp_n = wid & 3;
    const int mb = warp_m * 64;
    const int nb = warp_n * 96;

    const int ri = lane & 15;
    const uint32_t sega = (uint32_t)((lane >> 4) << 4);
    const uint32_t xpa  = (uint32_t)((ri & 7) << 4);
    const uint32_t a_root = (uint32_t)((mb + ri) * 128);

    const int rb = (lane & 7) + (((lane >> 4) & 1) << 3);
    const uint32_t segb = (uint32_t)(((lane >> 3) & 1) << 4);
    const uint32_t xpb  = (uint32_t)((rb & 7) << 4);
    const uint32_t b_root = (uint32_t)A_BYTES + (uint32_t)((nb + rb) * 128);

    float acc[4][12][4];
#pragma unroll
    for (int t = 0; t < 4; t++)
#pragma unroll
        for (int j = 0; j < 12; j++)
#pragma unroll
            for (int q = 0; q < 4; q++) acc[t][j][q] = 0.0f;

    // ---- prologue: stages 0,1 full; chunk 2 A-data in regs ----
    ldgA(0); stsA(0); cpB(0); CP_COMMIT();
    ldgA(1); stsA(1); cpB(1); CP_COMMIT();
    ldgA(2);

    for (int kc = 0; kc < KCHUNKS; kc++) {
        CP_WAIT1();
        __syncthreads();            // stage kc ready (A via prior syncs, B via wait)

        if (kc + 2 < KCHUNKS) { stsA(kc + 2); cpB(kc + 2); }
        CP_COMMIT();
        if (kc + 3 < KCHUNKS) ldgA(kc + 3);

        const uint32_t stb = sb + (uint32_t)(kc % 3) * STAGE_BYTES;
#pragma unroll
        for (int s = 0; s < 4; s++) {
            const uint32_t sbytes = (uint32_t)(s * 32);
            uint32_t bf[6][4];
#pragma unroll
            for (int jp = 0; jp < 6; jp++) {
                ldsm4(bf[jp], stb + b_root + (uint32_t)(jp * 2048) + ((sbytes + segb) ^ xpb));
            }
#pragma unroll
            for (int t = 0; t < 4; t++) {
                uint32_t af[4];
                ldsm4(af, stb + a_root + (uint32_t)(t * 2048) + ((sbytes + sega) ^ xpa));
#pragma unroll
                for (int j = 0; j < 12; j++) {
                    mma_tf32(acc[t][j], af, &bf[j >> 1][(j & 1) * 2]);
                }
            }
        }
    }

    CP_WAIT0();
    __syncthreads();

    // ---- spill gi to smem ----
    float* gi = reinterpret_cast<float*>(sb_ptr);
    {
        const int r0 = mb + (lane >> 2);
        const int c0 = nb + 2 * (lane & 3);
#pragma unroll
        for (int t = 0; t < 4; t++) {
            const int row = r0 + t * 16;
#pragma unroll
            for (int j = 0; j < 12; j++) {
                const int col = c0 + j * 8;
                gi[row * ROWP + col]           = acc[t][j][0];
                gi[row * ROWP + col + 1]       = acc[t][j][1];
                gi[(row + 8) * ROWP + col]     = acc[t][j][2];
                gi[(row + 8) * ROWP + col + 1] = acc[t][j][3];
            }
        }
    }
    __syncthreads();

    // ---- fused gate epilogue ----
    {
        const int row = tid >> 1;
        const int half = tid & 1;
        const float* gr = gi + row * ROWP;
        float a = 0.0f;
#pragma unroll 4
        for (int k = 0; k < 64; k++) {
            const int g = 2 * k + half;
            const float xr = gr[g] + s_br[g];
            const float xz = gr[128 + g] + s_bz[g];
            const float r  = 1.0f / (1.0f + __expf(-xr));
            const float zc = 1.0f / (1.0f + __expf(xz));          // 1 - z
            const float xn = gr[256 + g] + s_bni[g] + r * s_bnh[g];
            const float e  = __expf(-2.0f * fabsf(xn));
            float th = __fdividef(1.0f - e, 1.0f + e);
            th = copysignf(th, xn);
            a += s_lw[g] * zc * th;
        }
        a += __shfl_xor_sync(0xffffffffu, a, 1);
        if (half == 0) out[m0 + row] = a + lin_b[0];
    }
}

extern "C" void kernel_launch(void* const* d_in, const int* in_sizes, int n_in,
                              void* d_out, int out_size) {
    const float* x     = (const float*)d_in[0];
    const float* w_ih  = (const float*)d_in[1];
    // d_in[2] = weight_hh: mathematically dead (hidden state is always zero)
    const float* b_ih  = (const float*)d_in[3];
    const float* b_hh  = (const float*)d_in[4];
    const float* lin_w = (const float*)d_in[5];
    const float* lin_b = (const float*)d_in[6];
    float* out = (float*)d_out;

    wconv_kernel<<<384, 256>>>(w_ih);   // 384*1024 floats / (256*4)

    cudaFuncSetAttribute(ping_head_kernel,
                         cudaFuncAttributeMaxDynamicSharedMemorySize, SMEM_DYN);
    ping_head_kernel<<<512, 256, SMEM_DYN>>>(x, b_ih, b_hh, lin_w, lin_b, out);
}

// round 4
// speedup vs baseline: 1.3211x; 1.3211x over previous
#include <cuda_runtime.h>
#include <cstdint>

// ---------------------------------------------------------------------------
// PingHead on sm_103 (baseline target -> legacy mma.sync tf32 path).
// gi = x @ W_ih^T : M=65536, N=384, K=1024 ; fused GRU-gate epilogue.
// R4: pure ldsm+mma inner loop.
//   - W pre-rounded to tf32 once (rna) into __device__ global -> raw cp.async
//   - x fed raw fp32: HMMA.TF32 truncates operand mantissa (costs ~1.6x
//     rel_err, stays under 1e-3); zero cvt and zero staging regs in main loop
// ---------------------------------------------------------------------------

#define KCHUNKS 32
#define A_BYTES (128 * 128)                 // 128 rows x 32 f32
#define B_BYTES (384 * 128)                 // 384 rows x 32 f32
#define STAGE_BYTES (A_BYTES + B_BYTES)     // 64 KB
#define ROWP 385                            // gi row stride (floats)
#define GI_BYTES (128 * ROWP * 4)
#define SMEM_DYN (GI_BYTES + 1024)

__device__ float g_wtf32[384 * 1024];       // W_ih pre-rounded to tf32

__device__ __forceinline__ uint32_t smem_u32(const void* p) {
    uint32_t a;
    asm("{ .reg .u64 t; cvta.to.shared.u64 t, %1; cvt.u32.u64 %0, t; }" : "=r"(a) : "l"(p));
    return a;
}

__device__ __forceinline__ void cp_async16(uint32_t dst, const void* src) {
    asm volatile("cp.async.cg.shared.global [%0], [%1], 16;" :: "r"(dst), "l"(src) : "memory");
}
#define CP_COMMIT() asm volatile("cp.async.commit_group;" ::: "memory")
#define CP_WAIT1()  asm volatile("cp.async.wait_group 1;" ::: "memory")
#define CP_WAIT0()  asm volatile("cp.async.wait_group 0;" ::: "memory")

__device__ __forceinline__ void ldsm4(uint32_t* r, uint32_t addr) {
    asm volatile("ldmatrix.sync.aligned.m8n8.x4.shared.b16 {%0,%1,%2,%3}, [%4];"
                 : "=r"(r[0]), "=r"(r[1]), "=r"(r[2]), "=r"(r[3]) : "r"(addr));
}

__device__ __forceinline__ uint32_t cvt_tf32f(float f) {
    uint32_t r;
    asm("cvt.rna.tf32.f32 %0, %1;" : "=r"(r) : "f"(f));
    return r;
}

__device__ __forceinline__ void mma_tf32(float* d, const uint32_t* a, const uint32_t* b) {
    asm volatile("mma.sync.aligned.m16n8k8.row.col.f32.tf32.tf32.f32 "
                 "{%0,%1,%2,%3},{%4,%5,%6,%7},{%8,%9},{%0,%1,%2,%3};"
                 : "+f"(d[0]), "+f"(d[1]), "+f"(d[2]), "+f"(d[3])
                 : "r"(a[0]), "r"(a[1]), "r"(a[2]), "r"(a[3]), "r"(b[0]), "r"(b[1]));
}

// --- pre-kernel: round W to tf32 with rna (runs once per replay, ~2us) ---
__global__ void __launch_bounds__(256) wconv_kernel(const float* __restrict__ w) {
    const int i = (blockIdx.x * 256 + threadIdx.x) * 4;
    const float4 v = *reinterpret_cast<const float4*>(w + i);
    uint4 o = make_uint4(cvt_tf32f(v.x), cvt_tf32f(v.y), cvt_tf32f(v.z), cvt_tf32f(v.w));
    *reinterpret_cast<uint4*>(g_wtf32 + i) = o;
}

__global__ void __launch_bounds__(256, 1)
ping_head_kernel(const float* __restrict__ x,
                 const float* __restrict__ b_ih,
                 const float* __restrict__ b_hh,
                 const float* __restrict__ lin_w,
                 const float* __restrict__ lin_b,
                 float* __restrict__ out) {
    extern __shared__ char dsm[];
    __shared__ float s_br[128], s_bz[128], s_bni[128], s_bnh[128], s_lw[128];

    const int tid = threadIdx.x;
    const int wid = tid >> 5;
    const int lane = tid & 31;
    const int m0 = blockIdx.x * 128;

    const uint32_t dsm_u = smem_u32(dsm);
    const uint32_t sb = (dsm_u + 1023u) & ~1023u;   // 1KB-aligned smem base
    char* sb_ptr = dsm + (sb - dsm_u);

    if (tid < 128) {
        s_br[tid]  = b_ih[tid] + b_hh[tid];
        s_bz[tid]  = b_ih[128 + tid] + b_hh[128 + tid];
        s_bni[tid] = b_ih[256 + tid];
        s_bnh[tid] = b_hh[256 + tid];
        s_lw[tid]  = lin_w[tid];
    }

    // ---- stage copy: raw cp.async for A (fp32) and B (pre-tf32) ----
    auto copy_stage = [&](int kc) {
        const uint32_t sbase = sb + (uint32_t)(kc % 3) * STAGE_BYTES;
        const int koff = kc * 32;
#pragma unroll
        for (int ch = 0; ch < 16; ch++) {
            const int idx = tid + ch * 256;
            if (idx < 1024) {                      // A: 128 rows x 8 chunks
                const int row = idx >> 3, c = idx & 7;
                const float* src = x + (size_t)(m0 + row) * 1024 + koff + c * 4;
                const uint32_t doff = (uint32_t)(row * 128) +
                                      (((uint32_t)(c * 16)) ^ ((uint32_t)(row & 7) << 4));
                cp_async16(sbase + doff, src);
            } else {                               // B: 384 rows x 8 chunks
                const int bi = idx - 1024;
                const int row = bi >> 3, c = bi & 7;
                const float* src = g_wtf32 + (size_t)row * 1024 + koff + c * 4;
                const uint32_t doff = (uint32_t)A_BYTES + (uint32_t)(row * 128) +
                                      (((uint32_t)(c * 16)) ^ ((uint32_t)(row & 7) << 4));
                cp_async16(sbase + doff, src);
            }
        }
    };

    // ---- per-thread ldmatrix addressing (2m x 4n warp grid) ----
    const int warp_m = wid >> 2;
    const int warp_n = wid & 3;
    const int mb = warp_m * 64;
    const int nb = warp_n * 96;

    const int ri = lane & 15;
    const uint32_t sega = (uint32_t)((lane >> 4) << 4);
    const uint32_t xpa  = (uint32_t)((ri & 7) << 4);
    const uint32_t a_root = (uint32_t)((mb + ri) * 128);

    const int rb = (lane & 7) + (((lane >> 4) & 1) << 3);
    const uint32_t segb = (uint32_t)(((lane >> 3) & 1) << 4);
    const uint32_t xpb  = (uint32_t)((rb & 7) << 4);
    const uint32_t b_root = (uint32_t)A_BYTES + (uint32_t)((nb + rb) * 128);

    float acc[4][12][4];
#pragma unroll
    for (int t = 0; t < 4; t++)
#pragma unroll
        for (int j = 0; j < 12; j++)
#pragma unroll
            for (int q = 0; q < 4; q++) acc[t][j][q] = 0.0f;

    copy_stage(0); CP_COMMIT();
    copy_stage(1); CP_COMMIT();

    for (int kc = 0; kc < KCHUNKS; kc++) {
        CP_WAIT1();
        __syncthreads();
        if (kc + 2 < KCHUNKS) copy_stage(kc + 2);
        CP_COMMIT();

        const uint32_t stb = sb + (uint32_t)(kc % 3) * STAGE_BYTES;
#pragma unroll
        for (int s = 0; s < 4; s++) {
            const uint32_t sbytes = (uint32_t)(s * 32);
            uint32_t bf[6][4];
#pragma unroll
            for (int jp = 0; jp < 6; jp++) {
                ldsm4(bf[jp], stb + b_root + (uint32_t)(jp * 2048) + ((sbytes + segb) ^ xpb));
            }
#pragma unroll
            for (int t = 0; t < 4; t++) {
                uint32_t af[4];
                ldsm4(af, stb + a_root + (uint32_t)(t * 2048) + ((sbytes + sega) ^ xpa));
#pragma unroll
                for (int j = 0; j < 12; j++) {
                    mma_tf32(acc[t][j], af, &bf[j >> 1][(j & 1) * 2]);
                }
            }
        }
    }

    CP_WAIT0();
    __syncthreads();

    // ---- spill gi to smem ----
    float* gi = reinterpret_cast<float*>(sb_ptr);
    {
        const int r0 = mb + (lane >> 2);
        const int c0 = nb + 2 * (lane & 3);
#pragma unroll
        for (int t = 0; t < 4; t++) {
            const int row = r0 + t * 16;
#pragma unroll
            for (int j = 0; j < 12; j++) {
                const int col = c0 + j * 8;
                gi[row * ROWP + col]           = acc[t][j][0];
                gi[row * ROWP + col + 1]       = acc[t][j][1];
                gi[(row + 8) * ROWP + col]     = acc[t][j][2];
                gi[(row + 8) * ROWP + col + 1] = acc[t][j][3];
            }
        }
    }
    __syncthreads();

    // ---- fused gate epilogue ----
    {
        const int row = tid >> 1;
        const int half = tid & 1;
        const float* gr = gi + row * ROWP;
        float a = 0.0f;
#pragma unroll 4
        for (int k = 0; k < 64; k++) {
            const int g = 2 * k + half;
            const float xr = gr[g] + s_br[g];
            const float xz = gr[128 + g] + s_bz[g];
            const float r  = 1.0f / (1.0f + __expf(-xr));
            const float zc = 1.0f / (1.0f + __expf(xz));          // 1 - z
            const float xn = gr[256 + g] + s_bni[g] + r * s_bnh[g];
            const float e  = __expf(-2.0f * fabsf(xn));
            float th = __fdividef(1.0f - e, 1.0f + e);
            th = copysignf(th, xn);
            a += s_lw[g] * zc * th;
        }
        a += __shfl_xor_sync(0xffffffffu, a, 1);
        if (half == 0) out[m0 + row] = a + lin_b[0];
    }
}

extern "C" void kernel_launch(void* const* d_in, const int* in_sizes, int n_in,
                              void* d_out, int out_size) {
    const float* x     = (const float*)d_in[0];
    const float* w_ih  = (const float*)d_in[1];
    // d_in[2] = weight_hh: mathematically dead (hidden state is always zero)
    const float* b_ih  = (const float*)d_in[3];
    const float* b_hh  = (const float*)d_in[4];
    const float* lin_w = (const float*)d_in[5];
    const float* lin_b = (const float*)d_in[6];
    float* out = (float*)d_out;

    wconv_kernel<<<384, 256>>>(w_ih);   // 384*1024 floats / (256*4)

    cudaFuncSetAttribute(ping_head_kernel,
                         cudaFuncAttributeMaxDynamicSharedMemorySize, SMEM_DYN);
    ping_head_kernel<<<512, 256, SMEM_DYN>>>(x, b_ih, b_hh, lin_w, lin_b, out);
}